// round 7
// baseline (speedup 1.0000x reference)
#include <cuda_runtime.h>
#include <cuda_fp16.h>
#include <math.h>

// Problem constants (fixed for this dataset)
#define NN 50000
#define EE 800000
#define ET (EE + NN)      // 850000 edges incl. self loops
#define H1 4
#define C1 64
#define D1 256            // H1*C1
#define C2 64
#define IN1 128
#define NEG_SLOPE 0.2f

// ---------------- scratch (device globals, no runtime alloc) ----------------
__device__ __half2 g_h1h[(size_t)NN * D1 / 2];   // fp16 h1 (gather source)
__device__ float   g_acc1[(size_t)NN * D1];      // layer1 output (post bias+relu)
__device__ float   g_as1[NN * H1];
__device__ float   g_ad1[NN * H1];
__device__ __half2 g_h2h[(size_t)NN * C2 / 2];
__device__ float   g_as2[NN];
__device__ float   g_ad2[NN];
// CSR by dst
__device__ int g_deg[NN];
__device__ int g_cur[NN];
__device__ int g_row[NN + 1];
__device__ int g_srcs[ET];

__device__ __forceinline__ float lrelu(float v) {
    return v > 0.f ? v : NEG_SLOPE * v;
}

// ---------------- CSR build ----------------
__global__ void zero_counts_kernel() {
    int i = blockIdx.x * blockDim.x + threadIdx.x;
    if (i < NN) { g_deg[i] = 0; g_cur[i] = 0; }
}

__global__ void hist_kernel(const int* __restrict__ ei) {
    int e = blockIdx.x * blockDim.x + threadIdx.x;
    if (e >= ET) return;
    int d = (e < EE) ? ei[EE + e] : (e - EE);
    atomicAdd(&g_deg[d], 1);
}

// single-block exclusive scan of g_deg -> g_row  (1024 threads)
__global__ void scan_kernel() {
    __shared__ int warp_sums[32];
    const int CHUNK = (NN + 1023) / 1024;   // 49
    int t = threadIdx.x;
    int lane = t & 31, wid = t >> 5;
    int start = t * CHUNK;
    int local = 0;
    for (int i = 0; i < CHUNK; i++) {
        int idx = start + i;
        if (idx < NN) local += g_deg[idx];
    }
    int v = local;
    #pragma unroll
    for (int o = 1; o < 32; o <<= 1) {
        int n = __shfl_up_sync(0xFFFFFFFFu, v, o);
        if (lane >= o) v += n;
    }
    if (lane == 31) warp_sums[wid] = v;
    __syncthreads();
    if (wid == 0) {
        int w = warp_sums[lane];
        #pragma unroll
        for (int o = 1; o < 32; o <<= 1) {
            int n = __shfl_up_sync(0xFFFFFFFFu, w, o);
            if (lane >= o) w += n;
        }
        warp_sums[lane] = w;
    }
    __syncthreads();
    int excl = v - local + (wid > 0 ? warp_sums[wid - 1] : 0);
    int run = excl;
    for (int i = 0; i < CHUNK; i++) {
        int idx = start + i;
        if (idx < NN) {
            int dg = g_deg[idx];
            g_row[idx] = run;
            run += dg;
        }
    }
    if (t == 1023) g_row[NN] = run;   // == ET
}

__global__ void scatter_kernel(const int* __restrict__ ei) {
    int e = blockIdx.x * blockDim.x + threadIdx.x;
    if (e >= ET) return;
    int s, d;
    if (e < EE) { s = ei[e]; d = ei[EE + e]; } else { s = d = e - EE; }
    int pos = atomicAdd(&g_cur[d], 1);
    g_srcs[g_row[d] + pos] = s;
}

// ---------- SGEMM with fused fp16 store + attention-dot epilogue ----------
// C fp16 = A[M,K] @ B[K,N]; per-row attention dots for the block's BN=64
// column segment (one head per column block) written to as_out/ad_out.
#define BM 128
#define BN 64
#define BK 16

__global__ __launch_bounds__(256, 2)
void sgemm_fused_kernel(const float* __restrict__ A,
                        const float* __restrict__ B,
                        __half2* __restrict__ Ch,
                        const float* __restrict__ att_s,
                        const float* __restrict__ att_d,
                        float* __restrict__ as_out,
                        float* __restrict__ ad_out,
                        int M, int N, int K, int Hs) {
    __shared__ float As[2][BK][BM];      // 16 KB
    __shared__ float Bs[2][BK][BN];      // 8 KB
    const int tid = threadIdx.x;
    const int tx = tid & 15;             // col group (4 cols)
    const int ty = tid >> 4;             // row group (8 rows)
    const int row0 = blockIdx.y * BM, col0 = blockIdx.x * BN;

    const int af0 = tid, af1 = tid + 256;
    const int ar0 = af0 >> 2, ac0 = (af0 & 3) * 4;
    const int ar1 = af1 >> 2, ac1 = (af1 & 3) * 4;
    const int br = tid >> 4, bc = (tid & 15) * 4;

    const int nk = K / BK;
    float4 pa0, pa1, pb;

    {
        int gr0 = row0 + ar0, gr1 = row0 + ar1;
        pa0 = (gr0 < M) ? *reinterpret_cast<const float4*>(A + (size_t)gr0 * K + ac0)
                        : make_float4(0.f, 0.f, 0.f, 0.f);
        pa1 = (gr1 < M) ? *reinterpret_cast<const float4*>(A + (size_t)gr1 * K + ac1)
                        : make_float4(0.f, 0.f, 0.f, 0.f);
        pb = *reinterpret_cast<const float4*>(B + (size_t)br * N + col0 + bc);
        As[0][ac0 + 0][ar0] = pa0.x; As[0][ac0 + 1][ar0] = pa0.y;
        As[0][ac0 + 2][ar0] = pa0.z; As[0][ac0 + 3][ar0] = pa0.w;
        As[0][ac1 + 0][ar1] = pa1.x; As[0][ac1 + 1][ar1] = pa1.y;
        As[0][ac1 + 2][ar1] = pa1.z; As[0][ac1 + 3][ar1] = pa1.w;
        *reinterpret_cast<float4*>(&Bs[0][br][bc]) = pb;
    }
    __syncthreads();

    float acc[8][4] = {};
    int buf = 0;
    for (int kt = 0; kt < nk; kt++) {
        if (kt + 1 < nk) {
            int k0 = (kt + 1) * BK;
            int gr0 = row0 + ar0, gr1 = row0 + ar1;
            pa0 = (gr0 < M) ? *reinterpret_cast<const float4*>(A + (size_t)gr0 * K + k0 + ac0)
                            : make_float4(0.f, 0.f, 0.f, 0.f);
            pa1 = (gr1 < M) ? *reinterpret_cast<const float4*>(A + (size_t)gr1 * K + k0 + ac1)
                            : make_float4(0.f, 0.f, 0.f, 0.f);
            pb = *reinterpret_cast<const float4*>(B + (size_t)(k0 + br) * N + col0 + bc);
        }
        #pragma unroll
        for (int k = 0; k < BK; k++) {
            float a[8], b[4];
            *reinterpret_cast<float4*>(a)     = *reinterpret_cast<const float4*>(&As[buf][k][ty * 8]);
            *reinterpret_cast<float4*>(a + 4) = *reinterpret_cast<const float4*>(&As[buf][k][ty * 8 + 4]);
            *reinterpret_cast<float4*>(b)     = *reinterpret_cast<const float4*>(&Bs[buf][k][tx * 4]);
            #pragma unroll
            for (int i = 0; i < 8; i++)
                #pragma unroll
                for (int j = 0; j < 4; j++)
                    acc[i][j] += a[i] * b[j];
        }
        if (kt + 1 < nk) {
            int nb = buf ^ 1;
            As[nb][ac0 + 0][ar0] = pa0.x; As[nb][ac0 + 1][ar0] = pa0.y;
            As[nb][ac0 + 2][ar0] = pa0.z; As[nb][ac0 + 3][ar0] = pa0.w;
            As[nb][ac1 + 0][ar1] = pa1.x; As[nb][ac1 + 1][ar1] = pa1.y;
            As[nb][ac1 + 2][ar1] = pa1.z; As[nb][ac1 + 3][ar1] = pa1.w;
            *reinterpret_cast<float4*>(&Bs[nb][br][bc]) = pb;
            __syncthreads();
            buf = nb;
        }
    }

    // fp16 store
    #pragma unroll
    for (int i = 0; i < 8; i++) {
        int gr = row0 + ty * 8 + i;
        if (gr < M) {
            __half2* dst = Ch + ((size_t)gr * N + col0 + tx * 4) / 2;
            dst[0] = __floats2half2_rn(acc[i][0], acc[i][1]);
            dst[1] = __floats2half2_rn(acc[i][2], acc[i][3]);
        }
    }

    // fused attention dots: this block's columns = segment [col0, col0+BN)
    // of the attention vectors (one head per column block when N = H*BN).
    float sa4[4], da4[4];
    #pragma unroll
    for (int j = 0; j < 4; j++) {
        sa4[j] = att_s[col0 + tx * 4 + j];
        da4[j] = att_d[col0 + tx * 4 + j];
    }
    #pragma unroll
    for (int i = 0; i < 8; i++) {
        float ps = acc[i][0] * sa4[0] + acc[i][1] * sa4[1]
                 + acc[i][2] * sa4[2] + acc[i][3] * sa4[3];
        float pd = acc[i][0] * da4[0] + acc[i][1] * da4[1]
                 + acc[i][2] * da4[2] + acc[i][3] * da4[3];
        #pragma unroll
        for (int o = 1; o < 16; o <<= 1) {        // reduce across tx group
            ps += __shfl_xor_sync(0xFFFFFFFFu, ps, o);
            pd += __shfl_xor_sync(0xFFFFFFFFu, pd, o);
        }
        int gr = row0 + ty * 8 + i;
        if (tx == 0 && gr < M) {
            as_out[gr * Hs + blockIdx.x] = ps;
            ad_out[gr * Hs + blockIdx.x] = pd;
        }
    }
}

// ---------------- fused layer1: softmax + fp16 gather + bias + relu -------
// one warp per dst node; lane covers 8 cols (head = lane>>3).
// pass C: lanes precompute per-edge (src, alpha[4]) in parallel, inner loop
// uses register shuffles -> only one independent gather load per iteration.
__global__ void gat1_fused_kernel(const float* __restrict__ b1) {
    int w = (blockIdx.x * blockDim.x + threadIdx.x) >> 5;
    int lane = threadIdx.x & 31;
    if (w >= NN) return;
    int beg = g_row[w], end = g_row[w + 1];

    float4 adv = *reinterpret_cast<const float4*>(g_ad1 + w * H1);

    // pass A: per-head max over incoming edges
    float4 mx = make_float4(-INFINITY, -INFINITY, -INFINITY, -INFINITY);
    for (int i = beg + lane; i < end; i += 32) {
        int s = g_srcs[i];
        float4 a = *reinterpret_cast<const float4*>(g_as1 + s * H1);
        mx.x = fmaxf(mx.x, lrelu(a.x + adv.x));
        mx.y = fmaxf(mx.y, lrelu(a.y + adv.y));
        mx.z = fmaxf(mx.z, lrelu(a.z + adv.z));
        mx.w = fmaxf(mx.w, lrelu(a.w + adv.w));
    }
    #pragma unroll
    for (int o = 1; o < 32; o <<= 1) {
        mx.x = fmaxf(mx.x, __shfl_xor_sync(0xFFFFFFFFu, mx.x, o));
        mx.y = fmaxf(mx.y, __shfl_xor_sync(0xFFFFFFFFu, mx.y, o));
        mx.z = fmaxf(mx.z, __shfl_xor_sync(0xFFFFFFFFu, mx.z, o));
        mx.w = fmaxf(mx.w, __shfl_xor_sync(0xFFFFFFFFu, mx.w, o));
    }

    // pass B: per-head exp-sum
    float4 sm = make_float4(0.f, 0.f, 0.f, 0.f);
    for (int i = beg + lane; i < end; i += 32) {
        int s = g_srcs[i];
        float4 a = *reinterpret_cast<const float4*>(g_as1 + s * H1);
        sm.x += __expf(lrelu(a.x + adv.x) - mx.x);
        sm.y += __expf(lrelu(a.y + adv.y) - mx.y);
        sm.z += __expf(lrelu(a.z + adv.z) - mx.z);
        sm.w += __expf(lrelu(a.w + adv.w) - mx.w);
    }
    #pragma unroll
    for (int o = 1; o < 32; o <<= 1) {
        sm.x += __shfl_xor_sync(0xFFFFFFFFu, sm.x, o);
        sm.y += __shfl_xor_sync(0xFFFFFFFFu, sm.y, o);
        sm.z += __shfl_xor_sync(0xFFFFFFFFu, sm.z, o);
        sm.w += __shfl_xor_sync(0xFFFFFFFFu, sm.w, o);
    }
    float4 inv = make_float4(1.f / (sm.x + 1e-16f), 1.f / (sm.y + 1e-16f),
                             1.f / (sm.z + 1e-16f), 1.f / (sm.w + 1e-16f));

    int head = lane >> 3;
    float acc[8] = {};

    // pass C: chunked, shuffle-distributed
    for (int base = beg; base < end; base += 32) {
        int cnt = min(32, end - base);
        int s_r = 0;
        float4 al4 = make_float4(0.f, 0.f, 0.f, 0.f);
        if (base + lane < end) {
            s_r = g_srcs[base + lane];
            float4 a = *reinterpret_cast<const float4*>(g_as1 + s_r * H1);
            al4.x = __expf(lrelu(a.x + adv.x) - mx.x) * inv.x;
            al4.y = __expf(lrelu(a.y + adv.y) - mx.y) * inv.y;
            al4.z = __expf(lrelu(a.z + adv.z) - mx.z) * inv.z;
            al4.w = __expf(lrelu(a.w + adv.w) - mx.w) * inv.w;
        }
        for (int j = 0; j < cnt; j++) {
            int s    = __shfl_sync(0xFFFFFFFFu, s_r, j);
            float ax = __shfl_sync(0xFFFFFFFFu, al4.x, j);
            float ay = __shfl_sync(0xFFFFFFFFu, al4.y, j);
            float az = __shfl_sync(0xFFFFFFFFu, al4.z, j);
            float aw = __shfl_sync(0xFFFFFFFFu, al4.w, j);
            float alpha = (head == 0) ? ax : (head == 1) ? ay : (head == 2) ? az : aw;
            uint4 u = reinterpret_cast<const uint4*>(g_h1h + (size_t)s * (D1 / 2))[lane];
            float2 f0 = __half22float2(*reinterpret_cast<__half2*>(&u.x));
            float2 f1 = __half22float2(*reinterpret_cast<__half2*>(&u.y));
            float2 f2 = __half22float2(*reinterpret_cast<__half2*>(&u.z));
            float2 f3 = __half22float2(*reinterpret_cast<__half2*>(&u.w));
            acc[0] += f0.x * alpha; acc[1] += f0.y * alpha;
            acc[2] += f1.x * alpha; acc[3] += f1.y * alpha;
            acc[4] += f2.x * alpha; acc[5] += f2.y * alpha;
            acc[6] += f3.x * alpha; acc[7] += f3.y * alpha;
        }
    }

    int cb = lane * 8;
    float* op = g_acc1 + (size_t)w * D1 + cb;
    #pragma unroll
    for (int j = 0; j < 8; j++) {
        float v = acc[j] + b1[cb + j];
        op[j] = v > 0.f ? v : 0.f;
    }
}

// ---------------- fused layer2: softmax + fp16 gather + bias --------------
__global__ void gat2_fused_kernel(const float* __restrict__ b2,
                                  float* __restrict__ out) {
    int w = (blockIdx.x * blockDim.x + threadIdx.x) >> 5;
    int lane = threadIdx.x & 31;
    if (w >= NN) return;
    int beg = g_row[w], end = g_row[w + 1];

    float ad = g_ad2[w];

    float mxv = -INFINITY;
    for (int i = beg + lane; i < end; i += 32) {
        int s = g_srcs[i];
        mxv = fmaxf(mxv, lrelu(g_as2[s] + ad));
    }
    #pragma unroll
    for (int o = 1; o < 32; o <<= 1)
        mxv = fmaxf(mxv, __shfl_xor_sync(0xFFFFFFFFu, mxv, o));

    float smv = 0.f;
    for (int i = beg + lane; i < end; i += 32) {
        int s = g_srcs[i];
        smv += __expf(lrelu(g_as2[s] + ad) - mxv);
    }
    #pragma unroll
    for (int o = 1; o < 32; o <<= 1)
        smv += __shfl_xor_sync(0xFFFFFFFFu, smv, o);
    float inv = 1.f / (smv + 1e-16f);

    float a0 = 0.f, a1 = 0.f;
    for (int base = beg; base < end; base += 32) {
        int cnt = min(32, end - base);
        int s_r = 0;
        float al_r = 0.f;
        if (base + lane < end) {
            s_r = g_srcs[base + lane];
            al_r = __expf(lrelu(g_as2[s_r] + ad) - mxv) * inv;
        }
        for (int j = 0; j < cnt; j++) {
            int s       = __shfl_sync(0xFFFFFFFFu, s_r, j);
            float alpha = __shfl_sync(0xFFFFFFFFu, al_r, j);
            __half2 hv = g_h2h[(size_t)s * (C2 / 2) + lane];
            float2 v = __half22float2(hv);
            a0 += v.x * alpha;
            a1 += v.y * alpha;
        }
    }
    float* op = out + (size_t)w * C2 + 2 * lane;
    op[0] = a0 + b2[2 * lane];
    op[1] = a1 + b2[2 * lane + 1];
}

extern "C" void kernel_launch(void* const* d_in, const int* in_sizes, int n_in,
                              void* d_out, int out_size) {
    const float* x     = (const float*)d_in[0];
    const int*   ei    = (const int*)d_in[1];     // int32
    const float* W1    = (const float*)d_in[2];
    const float* at_s1 = (const float*)d_in[3];
    const float* at_d1 = (const float*)d_in[4];
    const float* b1    = (const float*)d_in[5];
    const float* W2    = (const float*)d_in[6];
    const float* at_s2 = (const float*)d_in[7];
    const float* at_d2 = (const float*)d_in[8];
    const float* b2    = (const float*)d_in[9];
    float* out = (float*)d_out;

    static float*   p_acc1 = nullptr;
    static __half2* p_h1h  = nullptr;
    static __half2* p_h2h  = nullptr;
    static float *p_as1, *p_ad1, *p_as2, *p_ad2;
    static cudaStream_t s_side = nullptr;
    static cudaEvent_t  ev_root = nullptr, ev_csr = nullptr;
    if (!p_acc1) {   // address lookup + stream/event creation (first call is
                     // the un-captured correctness run; no device mem alloc)
        cudaGetSymbolAddress((void**)&p_acc1, g_acc1);
        cudaGetSymbolAddress((void**)&p_h1h, g_h1h);
        cudaGetSymbolAddress((void**)&p_h2h, g_h2h);
        cudaGetSymbolAddress((void**)&p_as1, g_as1);
        cudaGetSymbolAddress((void**)&p_ad1, g_ad1);
        cudaGetSymbolAddress((void**)&p_as2, g_as2);
        cudaGetSymbolAddress((void**)&p_ad2, g_ad2);
        cudaStreamCreateWithFlags(&s_side, cudaStreamNonBlocking);
        cudaEventCreateWithFlags(&ev_root, cudaEventDisableTiming);
        cudaEventCreateWithFlags(&ev_csr, cudaEventDisableTiming);
    }

    // ---- fork: CSR build on side stream, overlapped with layer-1 GEMM ----
    cudaEventRecord(ev_root, (cudaStream_t)0);
    cudaStreamWaitEvent(s_side, ev_root, 0);
    zero_counts_kernel<<<(NN + 255) / 256, 256, 0, s_side>>>();
    hist_kernel<<<(ET + 255) / 256, 256, 0, s_side>>>(ei);
    scan_kernel<<<1, 1024, 0, s_side>>>();
    scatter_kernel<<<(ET + 255) / 256, 256, 0, s_side>>>(ei);
    cudaEventRecord(ev_csr, s_side);

    // ---- layer 1 (main stream) ----
    sgemm_fused_kernel<<<dim3(D1 / BN, (NN + BM - 1) / BM), 256>>>(
        x, W1, p_h1h, at_s1, at_d1, p_as1, p_ad1, NN, D1, IN1, H1);
    cudaStreamWaitEvent((cudaStream_t)0, ev_csr, 0);   // join CSR
    gat1_fused_kernel<<<(NN + 7) / 8, 256>>>(b1);

    // ---- layer 2 ----
    sgemm_fused_kernel<<<dim3(C2 / BN, (NN + BM - 1) / BM), 256>>>(
        p_acc1, W2, p_h2h, at_s2, at_d2, p_as2, p_ad2, NN, C2, D1, 1);
    gat2_fused_kernel<<<(NN + 7) / 8, 256>>>(b2, out);
}

// round 8
// speedup vs baseline: 1.0634x; 1.0634x over previous
#include <cuda_runtime.h>
#include <cuda_fp16.h>
#include <math.h>

// Problem constants (fixed for this dataset)
#define NN 50000
#define EE 800000
#define ET (EE + NN)      // 850000 edges incl. self loops
#define H1 4
#define C1 64
#define D1 256            // H1*C1
#define C2 64
#define IN1 128
#define NEG_SLOPE 0.2f

// ---------------- scratch (device globals, no runtime alloc) ----------------
__device__ __half2 g_h1h[(size_t)NN * D1 / 2];   // fp16 h1 (gather source)
__device__ float   g_acc1[(size_t)NN * D1];      // layer1 output (post bias+relu)
__device__ float   g_as1[NN * H1];
__device__ float   g_ad1[NN * H1];
__device__ __half2 g_h2h[(size_t)NN * C2 / 2];
__device__ float   g_as2[NN];
__device__ float   g_ad2[NN];
// CSR by dst
__device__ int g_deg[NN];
__device__ int g_cur[NN];
__device__ int g_row[NN + 1];
__device__ int g_srcs[ET];

__device__ __forceinline__ float lrelu(float v) {
    return v > 0.f ? v : NEG_SLOPE * v;
}

// online-softmax combine: (m1,s1) <- (m1,s1) ⊕ (m2,s2); NaN-safe for -inf pairs
__device__ __forceinline__ void osm_combine(float& m, float& s, float om, float os) {
    float nm = fmaxf(m, om);
    s = s * __expf(fmaxf(m - nm, -88.f)) + os * __expf(fmaxf(om - nm, -88.f));
    m = nm;
}

// ---------------- CSR build ----------------
__global__ void zero_counts_kernel() {
    int i = blockIdx.x * blockDim.x + threadIdx.x;
    if (i < NN) { g_deg[i] = 0; g_cur[i] = 0; }
}

__global__ void hist_kernel(const int* __restrict__ ei) {
    int e = blockIdx.x * blockDim.x + threadIdx.x;
    if (e >= ET) return;
    int d = (e < EE) ? ei[EE + e] : (e - EE);
    atomicAdd(&g_deg[d], 1);
}

// single-block exclusive scan of g_deg -> g_row  (1024 threads)
__global__ void scan_kernel() {
    __shared__ int warp_sums[32];
    const int CHUNK = (NN + 1023) / 1024;   // 49
    int t = threadIdx.x;
    int lane = t & 31, wid = t >> 5;
    int start = t * CHUNK;
    int local = 0;
    for (int i = 0; i < CHUNK; i++) {
        int idx = start + i;
        if (idx < NN) local += g_deg[idx];
    }
    int v = local;
    #pragma unroll
    for (int o = 1; o < 32; o <<= 1) {
        int n = __shfl_up_sync(0xFFFFFFFFu, v, o);
        if (lane >= o) v += n;
    }
    if (lane == 31) warp_sums[wid] = v;
    __syncthreads();
    if (wid == 0) {
        int w = warp_sums[lane];
        #pragma unroll
        for (int o = 1; o < 32; o <<= 1) {
            int n = __shfl_up_sync(0xFFFFFFFFu, w, o);
            if (lane >= o) w += n;
        }
        warp_sums[lane] = w;
    }
    __syncthreads();
    int excl = v - local + (wid > 0 ? warp_sums[wid - 1] : 0);
    int run = excl;
    for (int i = 0; i < CHUNK; i++) {
        int idx = start + i;
        if (idx < NN) {
            int dg = g_deg[idx];
            g_row[idx] = run;
            run += dg;
        }
    }
    if (t == 1023) g_row[NN] = run;   // == ET
}

__global__ void scatter_kernel(const int* __restrict__ ei) {
    int e = blockIdx.x * blockDim.x + threadIdx.x;
    if (e >= ET) return;
    int s, d;
    if (e < EE) { s = ei[e]; d = ei[EE + e]; } else { s = d = e - EE; }
    int pos = atomicAdd(&g_cur[d], 1);
    g_srcs[g_row[d] + pos] = s;
}

// ---------- SGEMM with fused fp16 store + attention-dot epilogue ----------
#define BM 128
#define BN 64
#define BK 16

__global__ __launch_bounds__(256, 2)
void sgemm_fused_kernel(const float* __restrict__ A,
                        const float* __restrict__ B,
                        __half2* __restrict__ Ch,
                        const float* __restrict__ att_s,
                        const float* __restrict__ att_d,
                        float* __restrict__ as_out,
                        float* __restrict__ ad_out,
                        int M, int N, int K, int Hs) {
    __shared__ float As[2][BK][BM];      // 16 KB
    __shared__ float Bs[2][BK][BN];      // 8 KB
    const int tid = threadIdx.x;
    const int tx = tid & 15;             // col group (4 cols)
    const int ty = tid >> 4;             // row group (8 rows)
    const int row0 = blockIdx.y * BM, col0 = blockIdx.x * BN;

    const int af0 = tid, af1 = tid + 256;
    const int ar0 = af0 >> 2, ac0 = (af0 & 3) * 4;
    const int ar1 = af1 >> 2, ac1 = (af1 & 3) * 4;
    const int br = tid >> 4, bc = (tid & 15) * 4;

    const int nk = K / BK;
    float4 pa0, pa1, pb;

    {
        int gr0 = row0 + ar0, gr1 = row0 + ar1;
        pa0 = (gr0 < M) ? *reinterpret_cast<const float4*>(A + (size_t)gr0 * K + ac0)
                        : make_float4(0.f, 0.f, 0.f, 0.f);
        pa1 = (gr1 < M) ? *reinterpret_cast<const float4*>(A + (size_t)gr1 * K + ac1)
                        : make_float4(0.f, 0.f, 0.f, 0.f);
        pb = *reinterpret_cast<const float4*>(B + (size_t)br * N + col0 + bc);
        As[0][ac0 + 0][ar0] = pa0.x; As[0][ac0 + 1][ar0] = pa0.y;
        As[0][ac0 + 2][ar0] = pa0.z; As[0][ac0 + 3][ar0] = pa0.w;
        As[0][ac1 + 0][ar1] = pa1.x; As[0][ac1 + 1][ar1] = pa1.y;
        As[0][ac1 + 2][ar1] = pa1.z; As[0][ac1 + 3][ar1] = pa1.w;
        *reinterpret_cast<float4*>(&Bs[0][br][bc]) = pb;
    }
    __syncthreads();

    float acc[8][4] = {};
    int buf = 0;
    for (int kt = 0; kt < nk; kt++) {
        if (kt + 1 < nk) {
            int k0 = (kt + 1) * BK;
            int gr0 = row0 + ar0, gr1 = row0 + ar1;
            pa0 = (gr0 < M) ? *reinterpret_cast<const float4*>(A + (size_t)gr0 * K + k0 + ac0)
                            : make_float4(0.f, 0.f, 0.f, 0.f);
            pa1 = (gr1 < M) ? *reinterpret_cast<const float4*>(A + (size_t)gr1 * K + k0 + ac1)
                            : make_float4(0.f, 0.f, 0.f, 0.f);
            pb = *reinterpret_cast<const float4*>(B + (size_t)(k0 + br) * N + col0 + bc);
        }
        #pragma unroll
        for (int k = 0; k < BK; k++) {
            float a[8], b[4];
            *reinterpret_cast<float4*>(a)     = *reinterpret_cast<const float4*>(&As[buf][k][ty * 8]);
            *reinterpret_cast<float4*>(a + 4) = *reinterpret_cast<const float4*>(&As[buf][k][ty * 8 + 4]);
            *reinterpret_cast<float4*>(b)     = *reinterpret_cast<const float4*>(&Bs[buf][k][tx * 4]);
            #pragma unroll
            for (int i = 0; i < 8; i++)
                #pragma unroll
                for (int j = 0; j < 4; j++)
                    acc[i][j] += a[i] * b[j];
        }
        if (kt + 1 < nk) {
            int nb = buf ^ 1;
            As[nb][ac0 + 0][ar0] = pa0.x; As[nb][ac0 + 1][ar0] = pa0.y;
            As[nb][ac0 + 2][ar0] = pa0.z; As[nb][ac0 + 3][ar0] = pa0.w;
            As[nb][ac1 + 0][ar1] = pa1.x; As[nb][ac1 + 1][ar1] = pa1.y;
            As[nb][ac1 + 2][ar1] = pa1.z; As[nb][ac1 + 3][ar1] = pa1.w;
            *reinterpret_cast<float4*>(&Bs[nb][br][bc]) = pb;
            __syncthreads();
            buf = nb;
        }
    }

    // fp16 store
    #pragma unroll
    for (int i = 0; i < 8; i++) {
        int gr = row0 + ty * 8 + i;
        if (gr < M) {
            __half2* dst = Ch + ((size_t)gr * N + col0 + tx * 4) / 2;
            dst[0] = __floats2half2_rn(acc[i][0], acc[i][1]);
            dst[1] = __floats2half2_rn(acc[i][2], acc[i][3]);
        }
    }

    // fused attention dots (one head per BN=64 column block)
    float sa4[4], da4[4];
    #pragma unroll
    for (int j = 0; j < 4; j++) {
        sa4[j] = att_s[col0 + tx * 4 + j];
        da4[j] = att_d[col0 + tx * 4 + j];
    }
    #pragma unroll
    for (int i = 0; i < 8; i++) {
        float ps = acc[i][0] * sa4[0] + acc[i][1] * sa4[1]
                 + acc[i][2] * sa4[2] + acc[i][3] * sa4[3];
        float pd = acc[i][0] * da4[0] + acc[i][1] * da4[1]
                 + acc[i][2] * da4[2] + acc[i][3] * da4[3];
        #pragma unroll
        for (int o = 1; o < 16; o <<= 1) {
            ps += __shfl_xor_sync(0xFFFFFFFFu, ps, o);
            pd += __shfl_xor_sync(0xFFFFFFFFu, pd, o);
        }
        int gr = row0 + ty * 8 + i;
        if (tx == 0 && gr < M) {
            as_out[gr * Hs + blockIdx.x] = ps;
            ad_out[gr * Hs + blockIdx.x] = pd;
        }
    }
}

// ---------------- fused layer1: online softmax + fp16 gather + bias + relu
// one warp per dst node; lane covers 8 cols (head = lane>>3)
__global__ void gat1_fused_kernel(const float* __restrict__ b1) {
    int w = (blockIdx.x * blockDim.x + threadIdx.x) >> 5;
    int lane = threadIdx.x & 31;
    if (w >= NN) return;
    int beg = g_row[w], end = g_row[w + 1];

    float4 adv = *reinterpret_cast<const float4*>(g_ad1 + w * H1);

    // single pass: online softmax (per-lane running max + rescaled sum)
    float4 mx = make_float4(-INFINITY, -INFINITY, -INFINITY, -INFINITY);
    float4 sm = make_float4(0.f, 0.f, 0.f, 0.f);
    for (int i = beg + lane; i < end; i += 32) {
        int s = g_srcs[i];
        float4 a = *reinterpret_cast<const float4*>(g_as1 + s * H1);
        float vx = lrelu(a.x + adv.x), vy = lrelu(a.y + adv.y);
        float vz = lrelu(a.z + adv.z), vw = lrelu(a.w + adv.w);
        float nx = fmaxf(mx.x, vx), ny = fmaxf(mx.y, vy);
        float nz = fmaxf(mx.z, vz), nw = fmaxf(mx.w, vw);
        sm.x = sm.x * __expf(mx.x - nx) + __expf(vx - nx);
        sm.y = sm.y * __expf(mx.y - ny) + __expf(vy - ny);
        sm.z = sm.z * __expf(mx.z - nz) + __expf(vz - nz);
        sm.w = sm.w * __expf(mx.w - nw) + __expf(vw - nw);
        mx.x = nx; mx.y = ny; mx.z = nz; mx.w = nw;
    }
    // lane combine
    #pragma unroll
    for (int o = 1; o < 32; o <<= 1) {
        float omx, osx;
        omx = __shfl_xor_sync(0xFFFFFFFFu, mx.x, o);
        osx = __shfl_xor_sync(0xFFFFFFFFu, sm.x, o);
        osm_combine(mx.x, sm.x, omx, osx);
        omx = __shfl_xor_sync(0xFFFFFFFFu, mx.y, o);
        osx = __shfl_xor_sync(0xFFFFFFFFu, sm.y, o);
        osm_combine(mx.y, sm.y, omx, osx);
        omx = __shfl_xor_sync(0xFFFFFFFFu, mx.z, o);
        osx = __shfl_xor_sync(0xFFFFFFFFu, sm.z, o);
        osm_combine(mx.z, sm.z, omx, osx);
        omx = __shfl_xor_sync(0xFFFFFFFFu, mx.w, o);
        osx = __shfl_xor_sync(0xFFFFFFFFu, sm.w, o);
        osm_combine(mx.w, sm.w, omx, osx);
    }

    int head = lane >> 3;
    float mh  = (head == 0) ? mx.x : (head == 1) ? mx.y : (head == 2) ? mx.z : mx.w;
    float shv = (head == 0) ? sm.x : (head == 1) ? sm.y : (head == 2) ? sm.z : sm.w;
    float adh = (head == 0) ? adv.x : (head == 1) ? adv.y : (head == 2) ? adv.z : adv.w;
    float inv = 1.f / (shv + 1e-16f);

    // pass C: direct per-edge gather + fp32 accumulate
    float acc[8] = {};
    #pragma unroll 2
    for (int i = beg; i < end; i++) {
        int s = g_srcs[i];                               // broadcast load
        float ash = g_as1[s * H1 + head];
        float alpha = __expf(lrelu(ash + adh) - mh) * inv;
        const uint4* hp = reinterpret_cast<const uint4*>(g_h1h + (size_t)s * (D1 / 2));
        uint4 u = hp[lane];
        float2 f0 = __half22float2(*reinterpret_cast<__half2*>(&u.x));
        float2 f1 = __half22float2(*reinterpret_cast<__half2*>(&u.y));
        float2 f2 = __half22float2(*reinterpret_cast<__half2*>(&u.z));
        float2 f3 = __half22float2(*reinterpret_cast<__half2*>(&u.w));
        acc[0] += f0.x * alpha; acc[1] += f0.y * alpha;
        acc[2] += f1.x * alpha; acc[3] += f1.y * alpha;
        acc[4] += f2.x * alpha; acc[5] += f2.y * alpha;
        acc[6] += f3.x * alpha; acc[7] += f3.y * alpha;
    }

    int cb = lane * 8;
    float* op = g_acc1 + (size_t)w * D1 + cb;
    #pragma unroll
    for (int j = 0; j < 8; j++) {
        float v = acc[j] + b1[cb + j];
        op[j] = v > 0.f ? v : 0.f;
    }
}

// ---------------- fused layer2: online softmax + fp16 gather + bias -------
__global__ void gat2_fused_kernel(const float* __restrict__ b2,
                                  float* __restrict__ out) {
    int w = (blockIdx.x * blockDim.x + threadIdx.x) >> 5;
    int lane = threadIdx.x & 31;
    if (w >= NN) return;
    int beg = g_row[w], end = g_row[w + 1];

    float ad = g_ad2[w];

    float mxv = -INFINITY, smv = 0.f;
    for (int i = beg + lane; i < end; i += 32) {
        int s = g_srcs[i];
        float v = lrelu(g_as2[s] + ad);
        float nm = fmaxf(mxv, v);
        smv = smv * __expf(mxv - nm) + __expf(v - nm);
        mxv = nm;
    }
    #pragma unroll
    for (int o = 1; o < 32; o <<= 1) {
        float om = __shfl_xor_sync(0xFFFFFFFFu, mxv, o);
        float os = __shfl_xor_sync(0xFFFFFFFFu, smv, o);
        osm_combine(mxv, smv, om, os);
    }
    float inv = 1.f / (smv + 1e-16f);

    float a0 = 0.f, a1 = 0.f;
    #pragma unroll 2
    for (int i = beg; i < end; i++) {
        int s = g_srcs[i];
        float alpha = __expf(lrelu(g_as2[s] + ad) - mxv) * inv;
        __half2 hv = g_h2h[(size_t)s * (C2 / 2) + lane];
        float2 v = __half22float2(hv);
        a0 += v.x * alpha;
        a1 += v.y * alpha;
    }
    float* op = out + (size_t)w * C2 + 2 * lane;
    op[0] = a0 + b2[2 * lane];
    op[1] = a1 + b2[2 * lane + 1];
}

extern "C" void kernel_launch(void* const* d_in, const int* in_sizes, int n_in,
                              void* d_out, int out_size) {
    const float* x     = (const float*)d_in[0];
    const int*   ei    = (const int*)d_in[1];     // int32
    const float* W1    = (const float*)d_in[2];
    const float* at_s1 = (const float*)d_in[3];
    const float* at_d1 = (const float*)d_in[4];
    const float* b1    = (const float*)d_in[5];
    const float* W2    = (const float*)d_in[6];
    const float* at_s2 = (const float*)d_in[7];
    const float* at_d2 = (const float*)d_in[8];
    const float* b2    = (const float*)d_in[9];
    float* out = (float*)d_out;

    static float*   p_acc1 = nullptr;
    static __half2* p_h1h  = nullptr;
    static __half2* p_h2h  = nullptr;
    static float *p_as1, *p_ad1, *p_as2, *p_ad2;
    static cudaStream_t s_side = nullptr;
    static cudaEvent_t  ev_root = nullptr, ev_csr = nullptr;
    if (!p_acc1) {   // address lookup + stream/event creation (first call is
                     // the un-captured correctness run; no device mem alloc)
        cudaGetSymbolAddress((void**)&p_acc1, g_acc1);
        cudaGetSymbolAddress((void**)&p_h1h, g_h1h);
        cudaGetSymbolAddress((void**)&p_h2h, g_h2h);
        cudaGetSymbolAddress((void**)&p_as1, g_as1);
        cudaGetSymbolAddress((void**)&p_ad1, g_ad1);
        cudaGetSymbolAddress((void**)&p_as2, g_as2);
        cudaGetSymbolAddress((void**)&p_ad2, g_ad2);
        cudaStreamCreateWithFlags(&s_side, cudaStreamNonBlocking);
        cudaEventCreateWithFlags(&ev_root, cudaEventDisableTiming);
        cudaEventCreateWithFlags(&ev_csr, cudaEventDisableTiming);
    }

    // ---- fork: CSR build on side stream, overlapped with layer-1 GEMM ----
    cudaEventRecord(ev_root, (cudaStream_t)0);
    cudaStreamWaitEvent(s_side, ev_root, 0);
    zero_counts_kernel<<<(NN + 255) / 256, 256, 0, s_side>>>();
    hist_kernel<<<(ET + 255) / 256, 256, 0, s_side>>>(ei);
    scan_kernel<<<1, 1024, 0, s_side>>>();
    scatter_kernel<<<(ET + 255) / 256, 256, 0, s_side>>>(ei);
    cudaEventRecord(ev_csr, s_side);

    // ---- layer 1 (main stream) ----
    sgemm_fused_kernel<<<dim3(D1 / BN, (NN + BM - 1) / BM), 256>>>(
        x, W1, p_h1h, at_s1, at_d1, p_as1, p_ad1, NN, D1, IN1, H1);
    cudaStreamWaitEvent((cudaStream_t)0, ev_csr, 0);   // join CSR
    gat1_fused_kernel<<<(NN + 7) / 8, 256>>>(b1);

    // ---- layer 2 ----
    sgemm_fused_kernel<<<dim3(C2 / BN, (NN + BM - 1) / BM), 256>>>(
        p_acc1, W2, p_h2h, at_s2, at_d2, p_as2, p_ad2, NN, C2, D1, 1);
    gat2_fused_kernel<<<(NN + 7) / 8, 256>>>(b2, out);
}